// round 4
// baseline (speedup 1.0000x reference)
#include <cuda_runtime.h>
#include <math.h>

#define DD   128
#define NMAX 50000
#define TM   64
#define KT   16

// ---- scratch (no allocations allowed; referenced directly from device code) ----
__device__ __align__(16) float g_x0[NMAX * DD];
__device__ __align__(16) float g_gm[NMAX * DD];
__device__ __align__(16) float g_ag[NMAX * DD];
__device__ __align__(16) float g_h [NMAX * DD];
__device__ float g_deg [NMAX];
__device__ float g_dinv[NMAX];

// ---- clip x into g_x0 ----
__global__ void k_prep(const float* __restrict__ x, int n4) {
    int i = blockIdx.x * blockDim.x + threadIdx.x;
    if (i >= n4) return;
    float4 v = ((const float4*)x)[i];
    v.x = fminf(fmaxf(v.x, -100.f), 100.f);
    v.y = fminf(fmaxf(v.y, -100.f), 100.f);
    v.z = fminf(fmaxf(v.z, -100.f), 100.f);
    v.w = fminf(fmaxf(v.w, -100.f), 100.f);
    ((float4*)g_x0)[i] = v;
}

__global__ void k_deg_init(int N) {
    int i = blockIdx.x * blockDim.x + threadIdx.x;
    if (i < N) g_deg[i] = 1.0f;   // self-loop
}

__global__ void k_deg(const int* __restrict__ ei, int E) {
    int e = blockIdx.x * blockDim.x + threadIdx.x;
    if (e < E) atomicAdd(&g_deg[ei[E + e]], 1.0f);
}

__global__ void k_dinv(int N) {
    int i = blockIdx.x * blockDim.x + threadIdx.x;
    if (i < N) g_dinv[i] = rsqrtf(g_deg[i]);
}

// ---- g_ag[i,:] = g_gm[i,:] * dinv[i]^2  (self-loop term; also serves as init) ----
__global__ void k_self(int n4) {
    int i = blockIdx.x * blockDim.x + threadIdx.x;
    if (i >= n4) return;
    float s = g_dinv[i >> 5]; s *= s;
    float4 v = ((const float4*)g_gm)[i];
    v.x *= s; v.y *= s; v.z *= s; v.w *= s;
    ((float4*)g_ag)[i] = v;
}

// ---- edge scatter: warp per edge, float4 vector atomics into g_ag ----
__global__ void k_scatter(const int* __restrict__ ei, int E) {
    int g = blockIdx.x * blockDim.x + threadIdx.x;
    int e = g >> 5;
    if (e >= E) return;
    int lane = g & 31;
    int s = ei[e];
    int d = ei[E + e];
    float norm = g_dinv[s] * g_dinv[d];
    float4 v = ((const float4*)g_gm)[(size_t)s * 32 + lane];
    v.x *= norm; v.y *= norm; v.z *= norm; v.w *= norm;
#if defined(__CUDA_ARCH__) && (__CUDA_ARCH__ >= 900)
    atomicAdd((float4*)(g_ag + (size_t)d * DD + lane * 4), v);
#else
    float* p = g_ag + (size_t)d * DD + lane * 4;
    atomicAdd(p + 0, v.x); atomicAdd(p + 1, v.y);
    atomicAdd(p + 2, v.z); atomicAdd(p + 3, v.w);
#endif
}

// ---- epilogue: g_h = relu(g_ag + b) [+ g_x0] ----
template <bool ADDX>
__global__ void k_epi(const float* __restrict__ bias, int n4) {
    int i = blockIdx.x * blockDim.x + threadIdx.x;
    if (i >= n4) return;
    int c4 = i & 31;
    float4 a = ((const float4*)g_ag)[i];
    float4 b = ((const float4*)bias)[c4];
    float4 o;
    o.x = fmaxf(a.x + b.x, 0.f);
    o.y = fmaxf(a.y + b.y, 0.f);
    o.z = fmaxf(a.z + b.z, 0.f);
    o.w = fmaxf(a.w + b.w, 0.f);
    if (ADDX) {
        float4 xv = ((const float4*)g_x0)[i];
        o.x += xv.x; o.y += xv.y; o.z += xv.z; o.w += xv.w;
    }
    ((float4*)g_h)[i] = o;
}

// ---- fp32 GEMM: C[M,128] = A[M,KTOT] @ W[KTOT,128]
// MODE 0: A = g_x0          -> g_gm
// MODE 1: A = g_h           -> g_gm
// MODE 2: A = [g_h | g_x0]  -> out = g_h * sigmoid(acc + bias)   (gate)
template <int KTOT, int MODE>
__global__ void __launch_bounds__(256)
k_gemm(const float* __restrict__ W, const float* __restrict__ bias,
       float* __restrict__ outp, int M) {
    __shared__ float As[KT][TM + 1];
    __shared__ __align__(16) float Bs[KT][DD];
    const int tid = threadIdx.x;
    const int tx = tid & 31;
    const int ty = tid >> 5;
    const int rowBase = blockIdx.x * TM;

    float acc[8][4];
#pragma unroll
    for (int r = 0; r < 8; r++)
#pragma unroll
        for (int c = 0; c < 4; c++) acc[r][c] = 0.f;

    for (int k0 = 0; k0 < KTOT; k0 += KT) {
        const float* A = (MODE == 0) ? g_x0 : ((MODE == 2 && k0 >= 128) ? g_x0 : g_h);
        // A tile: 64 rows x 16 k, transposed into As[k][row]
        {
            int r = tid >> 2;        // 0..63
            int q = tid & 3;         // float4 index within 16
            int row = rowBase + r;
            float4 v = make_float4(0.f, 0.f, 0.f, 0.f);
            if (row < M)
                v = *(const float4*)(A + (size_t)row * DD + (k0 & 127) + q * 4);
            As[q * 4 + 0][r] = v.x;
            As[q * 4 + 1][r] = v.y;
            As[q * 4 + 2][r] = v.z;
            As[q * 4 + 3][r] = v.w;
        }
        // B tile: 16 k x 128 n
        {
            int kk = tid >> 5;       // 0..7
            int c4 = tid & 31;
#pragma unroll
            for (int hh = 0; hh < 2; hh++) {
                int krow = kk + hh * 8;
                *(float4*)&Bs[krow][c4 * 4] =
                    *(const float4*)(W + (size_t)(k0 + krow) * DD + c4 * 4);
            }
        }
        __syncthreads();
#pragma unroll
        for (int kk = 0; kk < KT; kk++) {
            float4 b = *(float4*)&Bs[kk][tx * 4];
            float a[8];
#pragma unroll
            for (int r = 0; r < 8; r++) a[r] = As[kk][ty * 8 + r];
#pragma unroll
            for (int r = 0; r < 8; r++) {
                acc[r][0] += a[r] * b.x;
                acc[r][1] += a[r] * b.y;
                acc[r][2] += a[r] * b.z;
                acc[r][3] += a[r] * b.w;
            }
        }
        __syncthreads();
    }

    float* C = (MODE == 2) ? outp : g_gm;
    const int c0 = tx * 4;
#pragma unroll
    for (int r = 0; r < 8; r++) {
        int row = rowBase + ty * 8 + r;
        if (row >= M) continue;
        float4 o;
        if (MODE == 2) {
            float4 bg4 = *(const float4*)(bias + c0);
            float4 hv  = *(const float4*)(g_h + (size_t)row * DD + c0);
            o.x = hv.x / (1.f + expf(-(acc[r][0] + bg4.x)));
            o.y = hv.y / (1.f + expf(-(acc[r][1] + bg4.y)));
            o.z = hv.z / (1.f + expf(-(acc[r][2] + bg4.z)));
            o.w = hv.w / (1.f + expf(-(acc[r][3] + bg4.w)));
        } else {
            o.x = acc[r][0]; o.y = acc[r][1]; o.z = acc[r][2]; o.w = acc[r][3];
        }
        *(float4*)(C + (size_t)row * DD + c0) = o;
    }
}

extern "C" void kernel_launch(void* const* d_in, const int* in_sizes, int n_in,
                              void* d_out, int out_size) {
    const float* x  = (const float*)d_in[0];
    const int*   ei = (const int*)d_in[1];     // JAX default: int32 (x64 disabled)
    const float* W1 = (const float*)d_in[2];
    const float* b1 = (const float*)d_in[3];
    const float* W2 = (const float*)d_in[4];
    const float* b2 = (const float*)d_in[5];
    const float* Wg = (const float*)d_in[6];
    const float* bg = (const float*)d_in[7];
    float* out = (float*)d_out;

    const int N  = in_sizes[0] / DD;     // 50000
    const int E  = in_sizes[1] / 2;      // 800000
    const int n4 = N * (DD / 4);         // float4 count

    const int TB = 256;
    const int gN4   = (n4 + TB - 1) / TB;
    const int gN    = (N + TB - 1) / TB;
    const int gE    = (E + TB - 1) / TB;
    const int gScat = (int)(((long long)E * 32 + TB - 1) / TB);
    const int gGemm = (N + TM - 1) / TM;

    // prep
    k_prep<<<gN4, TB>>>(x, n4);
    k_deg_init<<<gN, TB>>>(N);
    k_deg<<<gE, TB>>>(ei, E);
    k_dinv<<<gN, TB>>>(N);

    // layer 1: gm = x0 @ W1; agg = self + scatter; h = relu(agg + b1)
    k_gemm<128, 0><<<gGemm, TB>>>(W1, nullptr, nullptr, N);
    k_self<<<gN4, TB>>>(n4);
    k_scatter<<<gScat, TB>>>(ei, E);
    k_epi<false><<<gN4, TB>>>(b1, n4);

    // layer 2: gm = h @ W2; agg = self + scatter; h = relu(agg + b2) + x0
    k_gemm<128, 1><<<gGemm, TB>>>(W2, nullptr, nullptr, N);
    k_self<<<gN4, TB>>>(n4);
    k_scatter<<<gScat, TB>>>(ei, E);
    k_epi<true><<<gN4, TB>>>(b2, n4);

    // gate: out = h * sigmoid([h|x0] @ Wg + bg)
    k_gemm<256, 2><<<gGemm, TB>>>(Wg, bg, out, N);
}

// round 5
// speedup vs baseline: 1.0400x; 1.0400x over previous
#include <cuda_runtime.h>
#include <math.h>

#define DD   128
#define NMAX 50000
#define TM   64
#define KT   16

// ---- scratch (no allocations allowed; referenced directly from device code) ----
__device__ __align__(16) float g_x0[NMAX * DD];
__device__ __align__(16) float g_gm[NMAX * DD];
__device__ __align__(16) float g_ag[NMAX * DD];
__device__ __align__(16) float g_h [NMAX * DD];
__device__ float g_deg [NMAX];
__device__ float g_dinv[NMAX];

// ---- clip x into g_x0 ----
__global__ void k_prep(const float* __restrict__ x, int n4) {
    int i = blockIdx.x * blockDim.x + threadIdx.x;
    if (i >= n4) return;
    float4 v = ((const float4*)x)[i];
    v.x = fminf(fmaxf(v.x, -100.f), 100.f);
    v.y = fminf(fmaxf(v.y, -100.f), 100.f);
    v.z = fminf(fmaxf(v.z, -100.f), 100.f);
    v.w = fminf(fmaxf(v.w, -100.f), 100.f);
    ((float4*)g_x0)[i] = v;
}

__global__ void k_deg_init(int N) {
    int i = blockIdx.x * blockDim.x + threadIdx.x;
    if (i < N) g_deg[i] = 1.0f;   // self-loop
}

__global__ void k_deg(const int* __restrict__ ei, int E) {
    int e = blockIdx.x * blockDim.x + threadIdx.x;
    if (e < E) atomicAdd(&g_deg[ei[E + e]], 1.0f);
}

__global__ void k_dinv(int N) {
    int i = blockIdx.x * blockDim.x + threadIdx.x;
    if (i < N) g_dinv[i] = rsqrtf(g_deg[i]);
}

// ---- edge scatter: warp per edge, float4 vector atomics into g_ag ----
__global__ void k_scatter(const int* __restrict__ ei, int E) {
    int g = blockIdx.x * blockDim.x + threadIdx.x;
    int e = g >> 5;
    if (e >= E) return;
    int lane = g & 31;
    int s = ei[e];
    int d = ei[E + e];
    float norm = g_dinv[s] * g_dinv[d];
    float4 v = ((const float4*)g_gm)[(size_t)s * 32 + lane];
    v.x *= norm; v.y *= norm; v.z *= norm; v.w *= norm;
    atomicAdd((float4*)(g_ag + (size_t)d * DD + lane * 4), v);
}

// ---- epilogue: g_h = relu(g_ag + b) [+ g_x0] ----
template <bool ADDX>
__global__ void k_epi(const float* __restrict__ bias, int n4) {
    int i = blockIdx.x * blockDim.x + threadIdx.x;
    if (i >= n4) return;
    int c4 = i & 31;
    float4 a = ((const float4*)g_ag)[i];
    float4 b = ((const float4*)bias)[c4];
    float4 o;
    o.x = fmaxf(a.x + b.x, 0.f);
    o.y = fmaxf(a.y + b.y, 0.f);
    o.z = fmaxf(a.z + b.z, 0.f);
    o.w = fmaxf(a.w + b.w, 0.f);
    if (ADDX) {
        float4 xv = ((const float4*)g_x0)[i];
        o.x += xv.x; o.y += xv.y; o.z += xv.z; o.w += xv.w;
    }
    ((float4*)g_h)[i] = o;
}

// ---- fp32 GEMM with packed f32x2 FMA: C[M,128] = A[M,KTOT] @ W[KTOT,128]
// MODE 0: A = g_x0          -> g_gm  and g_ag = gm * dinv^2 (fused self term)
// MODE 1: A = g_h           -> g_gm  and g_ag = gm * dinv^2
// MODE 2: A = [g_h | g_x0]  -> out = g_h * sigmoid(acc + bias)   (gate)
template <int KTOT, int MODE>
__global__ void __launch_bounds__(256)
k_gemm(const float* __restrict__ W, const float* __restrict__ bias,
       float* __restrict__ outp, int M) {
    __shared__ float As[KT][TM + 2];               // stride 66 floats: 8B-aligned rows
    __shared__ __align__(16) float Bs[KT][DD];
    const int tid = threadIdx.x;
    const int tx = tid & 31;
    const int ty = tid >> 5;
    const int rowBase = blockIdx.x * TM;

    // 4 row-pairs x 4 cols, each accumulator holds {row0, row1} packed f32x2
    unsigned long long acc2[4][4] = {};

    for (int k0 = 0; k0 < KTOT; k0 += KT) {
        const float* A = (MODE == 0) ? g_x0 : ((MODE == 2 && k0 >= 128) ? g_x0 : g_h);
        // A tile: 64 rows x 16 k, transposed into As[k][row]
        {
            int r = tid >> 2;        // 0..63
            int q = tid & 3;         // float4 index within 16
            int row = rowBase + r;
            float4 v = make_float4(0.f, 0.f, 0.f, 0.f);
            if (row < M)
                v = *(const float4*)(A + (size_t)row * DD + (k0 & 127) + q * 4);
            As[q * 4 + 0][r] = v.x;
            As[q * 4 + 1][r] = v.y;
            As[q * 4 + 2][r] = v.z;
            As[q * 4 + 3][r] = v.w;
        }
        // B tile: 16 k x 128 n
        {
            int kk = tid >> 5;       // 0..7
            int c4 = tid & 31;
#pragma unroll
            for (int hh = 0; hh < 2; hh++) {
                int krow = kk + hh * 8;
                *(float4*)&Bs[krow][c4 * 4] =
                    *(const float4*)(W + (size_t)(k0 + krow) * DD + c4 * 4);
            }
        }
        __syncthreads();
#pragma unroll
        for (int kk = 0; kk < KT; kk++) {
            float4 b = *(float4*)&Bs[kk][tx * 4];
            unsigned long long bb0, bb1, bb2, bb3;
            asm("mov.b64 %0, {%1, %1};" : "=l"(bb0) : "f"(b.x));
            asm("mov.b64 %0, {%1, %1};" : "=l"(bb1) : "f"(b.y));
            asm("mov.b64 %0, {%1, %1};" : "=l"(bb2) : "f"(b.z));
            asm("mov.b64 %0, {%1, %1};" : "=l"(bb3) : "f"(b.w));
            const unsigned long long* ap =
                (const unsigned long long*)&As[kk][ty * 8];
#pragma unroll
            for (int rp = 0; rp < 4; rp++) {
                unsigned long long av = ap[rp];   // {a[2rp], a[2rp+1]} packed
                asm("fma.rn.f32x2 %0, %1, %2, %0;" : "+l"(acc2[rp][0]) : "l"(av), "l"(bb0));
                asm("fma.rn.f32x2 %0, %1, %2, %0;" : "+l"(acc2[rp][1]) : "l"(av), "l"(bb1));
                asm("fma.rn.f32x2 %0, %1, %2, %0;" : "+l"(acc2[rp][2]) : "l"(av), "l"(bb2));
                asm("fma.rn.f32x2 %0, %1, %2, %0;" : "+l"(acc2[rp][3]) : "l"(av), "l"(bb3));
            }
        }
        __syncthreads();
    }

    float* C = (MODE == 2) ? outp : g_gm;
    const int c0 = tx * 4;
    union U { unsigned long long u; float2 f; };
#pragma unroll
    for (int rp = 0; rp < 4; rp++) {
#pragma unroll
        for (int hh = 0; hh < 2; hh++) {
            int row = rowBase + ty * 8 + rp * 2 + hh;
            if (row >= M) continue;
            float v[4];
#pragma unroll
            for (int c = 0; c < 4; c++) {
                U t; t.u = acc2[rp][c];
                v[c] = hh ? t.f.y : t.f.x;
            }
            float4 o;
            if (MODE == 2) {
                float4 bg4 = *(const float4*)(bias + c0);
                float4 hv  = *(const float4*)(g_h + (size_t)row * DD + c0);
                o.x = hv.x / (1.f + expf(-(v[0] + bg4.x)));
                o.y = hv.y / (1.f + expf(-(v[1] + bg4.y)));
                o.z = hv.z / (1.f + expf(-(v[2] + bg4.z)));
                o.w = hv.w / (1.f + expf(-(v[3] + bg4.w)));
                *(float4*)(C + (size_t)row * DD + c0) = o;
            } else {
                o.x = v[0]; o.y = v[1]; o.z = v[2]; o.w = v[3];
                *(float4*)(C + (size_t)row * DD + c0) = o;
                float dv = g_dinv[row]; dv *= dv;
                float4 sa;
                sa.x = o.x * dv; sa.y = o.y * dv; sa.z = o.z * dv; sa.w = o.w * dv;
                *(float4*)(g_ag + (size_t)row * DD + c0) = sa;
            }
        }
    }
}

extern "C" void kernel_launch(void* const* d_in, const int* in_sizes, int n_in,
                              void* d_out, int out_size) {
    const float* x  = (const float*)d_in[0];
    const int*   ei = (const int*)d_in[1];     // JAX default: int32 (x64 disabled)
    const float* W1 = (const float*)d_in[2];
    const float* b1 = (const float*)d_in[3];
    const float* W2 = (const float*)d_in[4];
    const float* b2 = (const float*)d_in[5];
    const float* Wg = (const float*)d_in[6];
    const float* bg = (const float*)d_in[7];
    float* out = (float*)d_out;

    const int N  = in_sizes[0] / DD;     // 50000
    const int E  = in_sizes[1] / 2;      // 800000
    const int n4 = N * (DD / 4);         // float4 count

    const int TB = 256;
    const int gN4   = (n4 + TB - 1) / TB;
    const int gN    = (N + TB - 1) / TB;
    const int gE    = (E + TB - 1) / TB;
    const int gScat = (int)(((long long)E * 32 + TB - 1) / TB);
    const int gGemm = (N + TM - 1) / TM;

    // prep
    k_prep<<<gN4, TB>>>(x, n4);
    k_deg_init<<<gN, TB>>>(N);
    k_deg<<<gE, TB>>>(ei, E);
    k_dinv<<<gN, TB>>>(N);

    // layer 1: gm = x0 @ W1 (epilogue writes gm and ag = gm*dinv^2); scatter; epi
    k_gemm<128, 0><<<gGemm, TB>>>(W1, nullptr, nullptr, N);
    k_scatter<<<gScat, TB>>>(ei, E);
    k_epi<false><<<gN4, TB>>>(b1, n4);

    // layer 2
    k_gemm<128, 1><<<gGemm, TB>>>(W2, nullptr, nullptr, N);
    k_scatter<<<gScat, TB>>>(ei, E);
    k_epi<true><<<gN4, TB>>>(b2, n4);

    // gate: out = h * sigmoid([h|x0] @ Wg + bg)
    k_gemm<256, 2><<<gGemm, TB>>>(Wg, bg, out, N);
}

// round 7
// speedup vs baseline: 1.0496x; 1.0092x over previous
#include <cuda_runtime.h>
#include <cuda_bf16.h>
#include <math.h>
#include <stdint.h>

#define DD   128
#define NMAX 50000

// ---- scratch ----
__device__ __align__(16) float g_x0[NMAX * DD];
__device__ __align__(16) float g_gm[NMAX * DD];
__device__ __align__(16) float g_ag[NMAX * DD];
__device__ __align__(16) float g_h [NMAX * DD];
__device__ float g_deg [NMAX];
__device__ float g_dinv[NMAX];
// W transposed [n=128][K] bf16 hi/lo splits
__device__ __align__(16) __nv_bfloat16 g_w1h[128 * 128];
__device__ __align__(16) __nv_bfloat16 g_w1l[128 * 128];
__device__ __align__(16) __nv_bfloat16 g_w2h[128 * 128];
__device__ __align__(16) __nv_bfloat16 g_w2l[128 * 128];
__device__ __align__(16) __nv_bfloat16 g_wgh[128 * 256];
__device__ __align__(16) __nv_bfloat16 g_wgl[128 * 256];

__device__ __forceinline__ uint32_t smem_u32(const void* p) {
    uint32_t a;
    asm("{ .reg .u64 t; cvta.to.shared.u64 t, %1; cvt.u32.u64 %0, t; }" : "=r"(a) : "l"(p));
    return a;
}
__device__ __forceinline__ void ldsm4(uint32_t* r, uint32_t addr) {
    asm volatile("ldmatrix.sync.aligned.m8n8.x4.shared.b16 {%0,%1,%2,%3}, [%4];"
        : "=r"(r[0]), "=r"(r[1]), "=r"(r[2]), "=r"(r[3]) : "r"(addr));
}
__device__ __forceinline__ void mma_bf16(float* d, const uint32_t* a, const uint32_t* b) {
    asm volatile("mma.sync.aligned.m16n8k16.row.col.f32.bf16.bf16.f32 "
        "{%0,%1,%2,%3}, {%4,%5,%6,%7}, {%8,%9}, {%0,%1,%2,%3};"
        : "+f"(d[0]), "+f"(d[1]), "+f"(d[2]), "+f"(d[3])
        : "r"(a[0]), "r"(a[1]), "r"(a[2]), "r"(a[3]), "r"(b[0]), "r"(b[1]));
}

// ================= elementwise kernels =================
__global__ void k_prep(const float* __restrict__ x, int n4) {
    int i = blockIdx.x * blockDim.x + threadIdx.x;
    if (i >= n4) return;
    float4 v = ((const float4*)x)[i];
    v.x = fminf(fmaxf(v.x, -100.f), 100.f);
    v.y = fminf(fmaxf(v.y, -100.f), 100.f);
    v.z = fminf(fmaxf(v.z, -100.f), 100.f);
    v.w = fminf(fmaxf(v.w, -100.f), 100.f);
    ((float4*)g_x0)[i] = v;
}
__global__ void k_deg_init(int N) {
    int i = blockIdx.x * blockDim.x + threadIdx.x;
    if (i < N) g_deg[i] = 1.0f;
}
__global__ void k_deg(const int* __restrict__ ei, int E) {
    int e = blockIdx.x * blockDim.x + threadIdx.x;
    if (e < E) atomicAdd(&g_deg[ei[E + e]], 1.0f);
}
__global__ void k_dinv(int N) {
    int i = blockIdx.x * blockDim.x + threadIdx.x;
    if (i < N) g_dinv[i] = rsqrtf(g_deg[i]);
}
// W[K][128] fp32 -> transposed [n][K] bf16 hi/lo
__global__ void k_wconv(const float* __restrict__ W, __nv_bfloat16* __restrict__ oh,
                        __nv_bfloat16* __restrict__ ol, int KW) {
    int i = blockIdx.x * blockDim.x + threadIdx.x;
    if (i >= KW * 128) return;
    int k = i / 128, n = i % 128;
    float w = W[i];
    __nv_bfloat16 h = __float2bfloat16(w);
    __nv_bfloat16 l = __float2bfloat16(w - __bfloat162float(h));
    oh[n * KW + k] = h;
    ol[n * KW + k] = l;
}
__global__ void k_scatter(const int* __restrict__ ei, int E) {
    int g = blockIdx.x * blockDim.x + threadIdx.x;
    int e = g >> 5;
    if (e >= E) return;
    int lane = g & 31;
    int s = ei[e];
    int d = ei[E + e];
    float norm = g_dinv[s] * g_dinv[d];
    float4 v = ((const float4*)g_gm)[(size_t)s * 32 + lane];
    v.x *= norm; v.y *= norm; v.z *= norm; v.w *= norm;
    atomicAdd((float4*)(g_ag + (size_t)d * DD + lane * 4), v);
}
template <bool ADDX>
__global__ void k_epi(const float* __restrict__ bias, int n4) {
    int i = blockIdx.x * blockDim.x + threadIdx.x;
    if (i >= n4) return;
    int c4 = i & 31;
    float4 a = ((const float4*)g_ag)[i];
    float4 b = ((const float4*)bias)[c4];
    float4 o;
    o.x = fmaxf(a.x + b.x, 0.f);
    o.y = fmaxf(a.y + b.y, 0.f);
    o.z = fmaxf(a.z + b.z, 0.f);
    o.w = fmaxf(a.w + b.w, 0.f);
    if (ADDX) {
        float4 xv = ((const float4*)g_x0)[i];
        o.x += xv.x; o.y += xv.y; o.z += xv.z; o.w += xv.w;
    }
    ((float4*)g_h)[i] = o;
}

// ================= mma.sync split-bf16 GEMM =================
// D[128,128] fp32 = A[128,K] @ W[K,128]; K=128 (MODE 0/1), 256 (MODE 2, two halves)
// MODE 0: A=g_x0 -> g_gm, g_ag = gm*dinv^2
// MODE 1: A=g_h  -> g_gm, g_ag = gm*dinv^2
// MODE 2: A=[g_h | g_x0] -> out = g_h * sigmoid(D + bias)
// SMEM: AH[32K] AL[32K] BH[32K] BL[32K]; rows of 256B (128 bf16), 16B-chunk
// swizzle: chunk' = chunk ^ (row & 7)
#define SMEM_SZ 131072

template <int MODE>
__global__ void __launch_bounds__(256, 1)
k_mgemm(const __nv_bfloat16* __restrict__ Wh, const __nv_bfloat16* __restrict__ Wl,
        const float* __restrict__ bias, float* __restrict__ outp, int M) {
    extern __shared__ char smem[];
    char* sAH = smem;
    char* sAL = smem + 32768;
    char* sBH = smem + 65536;
    char* sBL = smem + 98304;
    const uint32_t uAH = smem_u32(sAH);
    const uint32_t uAL = uAH + 32768;
    const uint32_t uBH = uAH + 65536;
    const uint32_t uBL = uAH + 98304;

    const int tid  = threadIdx.x;
    const int lane = tid & 31;
    const int wid  = tid >> 5;
    const int warpM = wid >> 2;          // 0..1  (64 rows each)
    const int warpN = wid & 3;           // 0..3  (32 cols each)
    const int rowBase = blockIdx.x * 128;
    constexpr int NH = (MODE == 2) ? 2 : 1;
    constexpr int BK = NH * 128;

    float acc[4][4][4] = {};             // [mt][nt][frag]

    // ldmatrix lane geometry (constant across ks/mt — r&7, n&7 invariant under +16)
    const int rA = warpM * 64 + (lane & 15);
    const int cA = lane >> 4;                                   // 0..1
    const int nB = warpN * 32 + (lane & 7) + ((lane >> 4) << 3);
    const int cB = (lane >> 3) & 1;

    for (int half = 0; half < NH; half++) {
        // --- A tile: fp32 -> split bf16, swizzled rows of 256B ---
        {
            const float* A = (MODE == 0) ? g_x0 : ((MODE == 2 && half == 1) ? g_x0 : g_h);
            int r = tid >> 1;
            int grow = rowBase + r;
            const float* arow = A + (size_t)grow * DD;
            int cb = (tid & 1) * 8;                 // chunk base (chunk = 8 cols)
            bool rok = grow < M;
#pragma unroll
            for (int j = 0; j < 8; j++) {
                int ch = cb + j;
                float4 v0 = make_float4(0.f, 0.f, 0.f, 0.f), v1 = v0;
                if (rok) {
                    v0 = *(const float4*)(arow + ch * 8);
                    v1 = *(const float4*)(arow + ch * 8 + 4);
                }
                __nv_bfloat162 h0 = __floats2bfloat162_rn(v0.x, v0.y);
                __nv_bfloat162 h1 = __floats2bfloat162_rn(v0.z, v0.w);
                __nv_bfloat162 h2 = __floats2bfloat162_rn(v1.x, v1.y);
                __nv_bfloat162 h3 = __floats2bfloat162_rn(v1.z, v1.w);
                float2 f0 = __bfloat1622float2(h0), f1 = __bfloat1622float2(h1);
                float2 f2 = __bfloat1622float2(h2), f3 = __bfloat1622float2(h3);
                __nv_bfloat162 l0 = __floats2bfloat162_rn(v0.x - f0.x, v0.y - f0.y);
                __nv_bfloat162 l1 = __floats2bfloat162_rn(v0.z - f1.x, v0.w - f1.y);
                __nv_bfloat162 l2 = __floats2bfloat162_rn(v1.x - f2.x, v1.y - f2.y);
                __nv_bfloat162 l3 = __floats2bfloat162_rn(v1.z - f3.x, v1.w - f3.y);
                int addr = r * 256 + ((ch ^ (r & 7)) << 4);
                *(uint4*)(sAH + addr) = make_uint4(*(uint32_t*)&h0, *(uint32_t*)&h1,
                                                   *(uint32_t*)&h2, *(uint32_t*)&h3);
                *(uint4*)(sAL + addr) = make_uint4(*(uint32_t*)&l0, *(uint32_t*)&l1,
                                                   *(uint32_t*)&l2, *(uint32_t*)&l3);
            }
        }
        // --- B tile: pre-split bf16 [n][BK] -> swizzled SMEM ---
        {
            int n = tid >> 1;
            int cb = (tid & 1) * 8;
            const __nv_bfloat16* bh = Wh + (size_t)n * BK + half * 128;
            const __nv_bfloat16* bl = Wl + (size_t)n * BK + half * 128;
#pragma unroll
            for (int j = 0; j < 8; j++) {
                int ch = cb + j;
                int addr = n * 256 + ((ch ^ (n & 7)) << 4);
                *(uint4*)(sBH + addr) = *(const uint4*)(bh + ch * 8);
                *(uint4*)(sBL + addr) = *(const uint4*)(bl + ch * 8);
            }
        }
        __syncthreads();

        // --- MMA mainloop: 8 k-steps of 16 ---
#pragma unroll
        for (int ks = 0; ks < 8; ks++) {
            uint32_t afh[4][4], afl[4][4];
            const int swzA = ((ks * 2 + cA) ^ (rA & 7)) << 4;
#pragma unroll
            for (int mt = 0; mt < 4; mt++) {
                int off = (rA + mt * 16) * 256 + swzA;
                ldsm4(afh[mt], uAH + off);
                ldsm4(afl[mt], uAL + off);
            }
            uint32_t bfh[4][2], bfl[4][2];
            const int swzB = ((ks * 2 + cB) ^ (nB & 7)) << 4;
#pragma unroll
            for (int np = 0; np < 2; np++) {
                int off = (nB + np * 16) * 256 + swzB;
                uint32_t t[4];
                ldsm4(t, uBH + off);
                bfh[np * 2][0] = t[0]; bfh[np * 2][1] = t[1];
                bfh[np * 2 + 1][0] = t[2]; bfh[np * 2 + 1][1] = t[3];
                ldsm4(t, uBL + off);
                bfl[np * 2][0] = t[0]; bfl[np * 2][1] = t[1];
                bfl[np * 2 + 1][0] = t[2]; bfl[np * 2 + 1][1] = t[3];
            }
#pragma unroll
            for (int mt = 0; mt < 4; mt++)
#pragma unroll
                for (int nt = 0; nt < 4; nt++) {
                    mma_bf16(acc[mt][nt], afh[mt], bfh[nt]);
                    mma_bf16(acc[mt][nt], afh[mt], bfl[nt]);
                    mma_bf16(acc[mt][nt], afl[mt], bfh[nt]);
                }
        }
        if (NH == 2) __syncthreads();   // protect SMEM before next half rewrites
    }

    // --- epilogue ---
    const int mbase = rowBase + warpM * 64;
    const int cb0 = warpN * 32 + (lane & 3) * 2;
    const int rl = lane >> 2;
#pragma unroll
    for (int mt = 0; mt < 4; mt++) {
#pragma unroll
        for (int sub = 0; sub < 2; sub++) {
            int row = mbase + mt * 16 + rl + sub * 8;
            if (row >= M) continue;
            if (MODE == 2) {
#pragma unroll
                for (int nt = 0; nt < 4; nt++) {
                    int col = cb0 + nt * 8;
                    float2 b2 = *(const float2*)(bias + col);
                    float2 h2 = *(const float2*)(g_h + (size_t)row * DD + col);
                    float2 o;
                    o.x = h2.x / (1.f + expf(-(acc[mt][nt][sub * 2 + 0] + b2.x)));
                    o.y = h2.y / (1.f + expf(-(acc[mt][nt][sub * 2 + 1] + b2.y)));
                    *(float2*)(outp + (size_t)row * DD + col) = o;
                }
            } else {
                float dv = g_dinv[row]; dv *= dv;
#pragma unroll
                for (int nt = 0; nt < 4; nt++) {
                    int col = cb0 + nt * 8;
                    float2 o;
                    o.x = acc[mt][nt][sub * 2 + 0];
                    o.y = acc[mt][nt][sub * 2 + 1];
                    *(float2*)(g_gm + (size_t)row * DD + col) = o;
                    float2 s;
                    s.x = o.x * dv; s.y = o.y * dv;
                    *(float2*)(g_ag + (size_t)row * DD + col) = s;
                }
            }
        }
    }
}

extern "C" void kernel_launch(void* const* d_in, const int* in_sizes, int n_in,
                              void* d_out, int out_size) {
    const float* x  = (const float*)d_in[0];
    const int*   ei = (const int*)d_in[1];
    const float* W1 = (const float*)d_in[2];
    const float* b1 = (const float*)d_in[3];
    const float* W2 = (const float*)d_in[4];
    const float* b2 = (const float*)d_in[5];
    const float* Wg = (const float*)d_in[6];
    const float* bg = (const float*)d_in[7];
    float* out = (float*)d_out;

    const int N  = in_sizes[0] / DD;     // 50000
    const int E  = in_sizes[1] / 2;      // 800000
    const int n4 = N * (DD / 4);

    cudaFuncSetAttribute(k_mgemm<0>, cudaFuncAttributeMaxDynamicSharedMemorySize, SMEM_SZ);
    cudaFuncSetAttribute(k_mgemm<1>, cudaFuncAttributeMaxDynamicSharedMemorySize, SMEM_SZ);
    cudaFuncSetAttribute(k_mgemm<2>, cudaFuncAttributeMaxDynamicSharedMemorySize, SMEM_SZ);

    const int TB = 256;
    const int gN4   = (n4 + TB - 1) / TB;
    const int gN    = (N + TB - 1) / TB;
    const int gE    = (E + TB - 1) / TB;
    const int gScat = (int)(((long long)E * 32 + TB - 1) / TB);
    const int gT    = (N + 127) / 128;

    __nv_bfloat16 *w1h, *w1l, *w2h, *w2l, *wgh, *wgl;
    cudaGetSymbolAddress((void**)&w1h, g_w1h);
    cudaGetSymbolAddress((void**)&w1l, g_w1l);
    cudaGetSymbolAddress((void**)&w2h, g_w2h);
    cudaGetSymbolAddress((void**)&w2l, g_w2l);
    cudaGetSymbolAddress((void**)&wgh, g_wgh);
    cudaGetSymbolAddress((void**)&wgl, g_wgl);

    // prep
    k_prep<<<gN4, TB>>>(x, n4);
    k_deg_init<<<gN, TB>>>(N);
    k_deg<<<gE, TB>>>(ei, E);
    k_dinv<<<gN, TB>>>(N);
    k_wconv<<<(128 * 128 + TB - 1) / TB, TB>>>(W1, w1h, w1l, 128);
    k_wconv<<<(128 * 128 + TB - 1) / TB, TB>>>(W2, w2h, w2l, 128);
    k_wconv<<<(256 * 128 + TB - 1) / TB, TB>>>(Wg, wgh, wgl, 256);

    // layer 1
    k_mgemm<0><<<gT, 256, SMEM_SZ>>>(w1h, w1l, nullptr, nullptr, N);
    k_scatter<<<gScat, TB>>>(ei, E);
    k_epi<false><<<gN4, TB>>>(b1, n4);

    // layer 2
    k_mgemm<1><<<gT, 256, SMEM_SZ>>>(w2h, w2l, nullptr, nullptr, N);
    k_scatter<<<gScat, TB>>>(ei, E);
    k_epi<true><<<gN4, TB>>>(b2, n4);

    // gate
    k_mgemm<2><<<gT, 256, SMEM_SZ>>>(wgh, wgl, bg, out, N);
}

// round 8
// speedup vs baseline: 1.2200x; 1.1623x over previous
#include <cuda_runtime.h>
#include <cuda_bf16.h>
#include <math.h>
#include <stdint.h>

#define DD   128
#define NMAX 50000
#define EMAX 800000

// ---- scratch ----
__device__ __align__(16) float g_x0[NMAX * DD];
__device__ __align__(16) float g_gm[NMAX * DD];
__device__ __align__(16) float g_h [NMAX * DD];
__device__ float g_dinv[NMAX];
__device__ int   g_cnt [NMAX];
__device__ int   g_off [NMAX + 1];
__device__ int   g_cur [NMAX];
__device__ int   g_csrc [EMAX];
__device__ float g_cnorm[EMAX];
// W transposed [n=128][K] bf16 hi/lo splits
__device__ __align__(16) __nv_bfloat16 g_w1h[128 * 128];
__device__ __align__(16) __nv_bfloat16 g_w1l[128 * 128];
__device__ __align__(16) __nv_bfloat16 g_w2h[128 * 128];
__device__ __align__(16) __nv_bfloat16 g_w2l[128 * 128];
__device__ __align__(16) __nv_bfloat16 g_wgh[128 * 256];
__device__ __align__(16) __nv_bfloat16 g_wgl[128 * 256];

__device__ __forceinline__ uint32_t smem_u32(const void* p) {
    uint32_t a;
    asm("{ .reg .u64 t; cvta.to.shared.u64 t, %1; cvt.u32.u64 %0, t; }" : "=r"(a) : "l"(p));
    return a;
}
__device__ __forceinline__ void ldsm4(uint32_t* r, uint32_t addr) {
    asm volatile("ldmatrix.sync.aligned.m8n8.x4.shared.b16 {%0,%1,%2,%3}, [%4];"
        : "=r"(r[0]), "=r"(r[1]), "=r"(r[2]), "=r"(r[3]) : "r"(addr));
}
__device__ __forceinline__ void mma_bf16(float* d, const uint32_t* a, const uint32_t* b) {
    asm volatile("mma.sync.aligned.m16n8k16.row.col.f32.bf16.bf16.f32 "
        "{%0,%1,%2,%3}, {%4,%5,%6,%7}, {%8,%9}, {%0,%1,%2,%3};"
        : "+f"(d[0]), "+f"(d[1]), "+f"(d[2]), "+f"(d[3])
        : "r"(a[0]), "r"(a[1]), "r"(a[2]), "r"(a[3]), "r"(b[0]), "r"(b[1]));
}

// ================= prep kernels =================
__global__ void k_prep(const float* __restrict__ x, int n4) {
    int i = blockIdx.x * blockDim.x + threadIdx.x;
    if (i >= n4) return;
    float4 v = ((const float4*)x)[i];
    v.x = fminf(fmaxf(v.x, -100.f), 100.f);
    v.y = fminf(fmaxf(v.y, -100.f), 100.f);
    v.z = fminf(fmaxf(v.z, -100.f), 100.f);
    v.w = fminf(fmaxf(v.w, -100.f), 100.f);
    ((float4*)g_x0)[i] = v;
}
__global__ void k_cnt_init(int N) {
    int i = blockIdx.x * blockDim.x + threadIdx.x;
    if (i < N) g_cnt[i] = 0;
}
__global__ void k_cnt(const int* __restrict__ ei, int E) {
    int e = blockIdx.x * blockDim.x + threadIdx.x;
    if (e < E) atomicAdd(&g_cnt[ei[E + e]], 1);
}
__global__ void k_dinv(int N) {
    int i = blockIdx.x * blockDim.x + threadIdx.x;
    if (i < N) g_dinv[i] = rsqrtf(1.0f + (float)g_cnt[i]);   // +1 self-loop
}
// single-block exclusive scan of g_cnt -> g_off (and g_cur copy)
__global__ void __launch_bounds__(1024) k_scan(int N) {
    __shared__ int part[1024];
    const int tid = threadIdx.x;
    const int chunk = (N + 1023) / 1024;
    int lo = tid * chunk, hi = min(lo + chunk, N);
    int s = 0;
    for (int i = lo; i < hi; i++) s += g_cnt[i];
    part[tid] = s;
    __syncthreads();
    for (int d = 1; d < 1024; d <<= 1) {
        int t = (tid >= d) ? part[tid - d] : 0;
        __syncthreads();
        part[tid] += t;
        __syncthreads();
    }
    int base = part[tid] - s;     // exclusive prefix
    for (int i = lo; i < hi; i++) {
        g_off[i] = base;
        g_cur[i] = base;
        base += g_cnt[i];
    }
    if (tid == 1023) g_off[N] = base;
}
__global__ void k_fill(const int* __restrict__ ei, int E) {
    int e = blockIdx.x * blockDim.x + threadIdx.x;
    if (e >= E) return;
    int s = ei[e];
    int d = ei[E + e];
    int pos = atomicAdd(&g_cur[d], 1);
    g_csrc[pos] = s;
    g_cnorm[pos] = g_dinv[s] * g_dinv[d];
}
// W[K][128] fp32 -> transposed [n][K] bf16 hi/lo
__global__ void k_wconv(const float* __restrict__ W, __nv_bfloat16* __restrict__ oh,
                        __nv_bfloat16* __restrict__ ol, int KW) {
    int i = blockIdx.x * blockDim.x + threadIdx.x;
    if (i >= KW * 128) return;
    int k = i / 128, n = i % 128;
    float w = W[i];
    __nv_bfloat16 h = __float2bfloat16(w);
    __nv_bfloat16 l = __float2bfloat16(w - __bfloat162float(h));
    oh[n * KW + k] = h;
    ol[n * KW + k] = l;
}

// ================= pull aggregation (CSR), fused epilogue =================
// g_h[d,:] = relu( gm[d]*dinv[d]^2 + sum_e gm[src_e]*norm_e + bias ) [+ x0[d]]
template <bool ADDX>
__global__ void __launch_bounds__(256) k_pull(const float* __restrict__ bias, int N) {
    const int lane = threadIdx.x & 31;
    const int d = blockIdx.x * 8 + (threadIdx.x >> 5);
    if (d >= N) return;
    float dv = g_dinv[d]; dv *= dv;
    float4 acc = ((const float4*)g_gm)[(size_t)d * 32 + lane];
    acc.x *= dv; acc.y *= dv; acc.z *= dv; acc.w *= dv;
    const int beg = g_off[d], end = g_off[d + 1];
#pragma unroll 2
    for (int i = beg; i < end; i++) {
        int s = g_csrc[i];
        float nm = g_cnorm[i];
        float4 v = ((const float4*)g_gm)[(size_t)s * 32 + lane];
        acc.x += v.x * nm; acc.y += v.y * nm;
        acc.z += v.z * nm; acc.w += v.w * nm;
    }
    float4 b = ((const float4*)bias)[lane];
    float4 o;
    o.x = fmaxf(acc.x + b.x, 0.f);
    o.y = fmaxf(acc.y + b.y, 0.f);
    o.z = fmaxf(acc.z + b.z, 0.f);
    o.w = fmaxf(acc.w + b.w, 0.f);
    if (ADDX) {
        float4 xv = ((const float4*)g_x0)[(size_t)d * 32 + lane];
        o.x += xv.x; o.y += xv.y; o.z += xv.z; o.w += xv.w;
    }
    ((float4*)g_h)[(size_t)d * 32 + lane] = o;
}

// ================= mma.sync split-bf16 GEMM =================
// MODE 0: A=g_x0 -> g_gm;  MODE 1: A=g_h -> g_gm
// MODE 2: A=[g_h | g_x0] -> out = g_h * sigmoid(D + bias)
#define SMEM_SZ 131072

template <int MODE>
__global__ void __launch_bounds__(256, 1)
k_mgemm(const __nv_bfloat16* __restrict__ Wh, const __nv_bfloat16* __restrict__ Wl,
        const float* __restrict__ bias, float* __restrict__ outp, int M) {
    extern __shared__ char smem[];
    char* sAH = smem;
    char* sAL = smem + 32768;
    char* sBH = smem + 65536;
    char* sBL = smem + 98304;
    const uint32_t uAH = smem_u32(sAH);
    const uint32_t uAL = uAH + 32768;
    const uint32_t uBH = uAH + 65536;
    const uint32_t uBL = uAH + 98304;

    const int tid  = threadIdx.x;
    const int lane = tid & 31;
    const int wid  = tid >> 5;
    const int warpM = wid >> 2;
    const int warpN = wid & 3;
    const int rowBase = blockIdx.x * 128;
    constexpr int NH = (MODE == 2) ? 2 : 1;
    constexpr int BK = NH * 128;

    float acc[4][4][4] = {};

    const int rA = warpM * 64 + (lane & 15);
    const int cA = lane >> 4;
    const int nB = warpN * 32 + (lane & 7) + ((lane >> 4) << 3);
    const int cB = (lane >> 3) & 1;

    for (int half = 0; half < NH; half++) {
        {
            const float* A = (MODE == 0) ? g_x0 : ((MODE == 2 && half == 1) ? g_x0 : g_h);
            int r = tid >> 1;
            int grow = rowBase + r;
            const float* arow = A + (size_t)grow * DD;
            int cb = (tid & 1) * 8;
            bool rok = grow < M;
#pragma unroll
            for (int j = 0; j < 8; j++) {
                int ch = cb + j;
                float4 v0 = make_float4(0.f, 0.f, 0.f, 0.f), v1 = v0;
                if (rok) {
                    v0 = *(const float4*)(arow + ch * 8);
                    v1 = *(const float4*)(arow + ch * 8 + 4);
                }
                __nv_bfloat162 h0 = __floats2bfloat162_rn(v0.x, v0.y);
                __nv_bfloat162 h1 = __floats2bfloat162_rn(v0.z, v0.w);
                __nv_bfloat162 h2 = __floats2bfloat162_rn(v1.x, v1.y);
                __nv_bfloat162 h3 = __floats2bfloat162_rn(v1.z, v1.w);
                float2 f0 = __bfloat1622float2(h0), f1 = __bfloat1622float2(h1);
                float2 f2 = __bfloat1622float2(h2), f3 = __bfloat1622float2(h3);
                __nv_bfloat162 l0 = __floats2bfloat162_rn(v0.x - f0.x, v0.y - f0.y);
                __nv_bfloat162 l1 = __floats2bfloat162_rn(v0.z - f1.x, v0.w - f1.y);
                __nv_bfloat162 l2 = __floats2bfloat162_rn(v1.x - f2.x, v1.y - f2.y);
                __nv_bfloat162 l3 = __floats2bfloat162_rn(v1.z - f3.x, v1.w - f3.y);
                int addr = r * 256 + ((ch ^ (r & 7)) << 4);
                *(uint4*)(sAH + addr) = make_uint4(*(uint32_t*)&h0, *(uint32_t*)&h1,
                                                   *(uint32_t*)&h2, *(uint32_t*)&h3);
                *(uint4*)(sAL + addr) = make_uint4(*(uint32_t*)&l0, *(uint32_t*)&l1,
                                                   *(uint32_t*)&l2, *(uint32_t*)&l3);
            }
        }
        {
            int n = tid >> 1;
            int cb = (tid & 1) * 8;
            const __nv_bfloat16* bh = Wh + (size_t)n * BK + half * 128;
            const __nv_bfloat16* bl = Wl + (size_t)n * BK + half * 128;
#pragma unroll
            for (int j = 0; j < 8; j++) {
                int ch = cb + j;
                int addr = n * 256 + ((ch ^ (n & 7)) << 4);
                *(uint4*)(sBH + addr) = *(const uint4*)(bh + ch * 8);
                *(uint4*)(sBL + addr) = *(const uint4*)(bl + ch * 8);
            }
        }
        __syncthreads();

#pragma unroll
        for (int ks = 0; ks < 8; ks++) {
            uint32_t afh[4][4], afl[4][4];
            const int swzA = ((ks * 2 + cA) ^ (rA & 7)) << 4;
#pragma unroll
            for (int mt = 0; mt < 4; mt++) {
                int off = (rA + mt * 16) * 256 + swzA;
                ldsm4(afh[mt], uAH + off);
                ldsm4(afl[mt], uAL + off);
            }
            uint32_t bfh[4][2], bfl[4][2];
            const int swzB = ((ks * 2 + cB) ^ (nB & 7)) << 4;
#pragma unroll
            for (int np = 0; np < 2; np++) {
                int off = (nB + np * 16) * 256 + swzB;
                uint32_t t[4];
                ldsm4(t, uBH + off);
                bfh[np * 2][0] = t[0]; bfh[np * 2][1] = t[1];
                bfh[np * 2 + 1][0] = t[2]; bfh[np * 2 + 1][1] = t[3];
                ldsm4(t, uBL + off);
                bfl[np * 2][0] = t[0]; bfl[np * 2][1] = t[1];
                bfl[np * 2 + 1][0] = t[2]; bfl[np * 2 + 1][1] = t[3];
            }
#pragma unroll
            for (int mt = 0; mt < 4; mt++)
#pragma unroll
                for (int nt = 0; nt < 4; nt++) {
                    mma_bf16(acc[mt][nt], afh[mt], bfh[nt]);
                    mma_bf16(acc[mt][nt], afh[mt], bfl[nt]);
                    mma_bf16(acc[mt][nt], afl[mt], bfh[nt]);
                }
        }
        if (NH == 2) __syncthreads();
    }

    const int mbase = rowBase + warpM * 64;
    const int cb0 = warpN * 32 + (lane & 3) * 2;
    const int rl = lane >> 2;
#pragma unroll
    for (int mt = 0; mt < 4; mt++) {
#pragma unroll
        for (int sub = 0; sub < 2; sub++) {
            int row = mbase + mt * 16 + rl + sub * 8;
            if (row >= M) continue;
            if (MODE == 2) {
#pragma unroll
                for (int nt = 0; nt < 4; nt++) {
                    int col = cb0 + nt * 8;
                    float2 b2 = *(const float2*)(bias + col);
                    float2 h2 = *(const float2*)(g_h + (size_t)row * DD + col);
                    float2 o;
                    o.x = h2.x / (1.f + expf(-(acc[mt][nt][sub * 2 + 0] + b2.x)));
                    o.y = h2.y / (1.f + expf(-(acc[mt][nt][sub * 2 + 1] + b2.y)));
                    *(float2*)(outp + (size_t)row * DD + col) = o;
                }
            } else {
#pragma unroll
                for (int nt = 0; nt < 4; nt++) {
                    int col = cb0 + nt * 8;
                    float2 o;
                    o.x = acc[mt][nt][sub * 2 + 0];
                    o.y = acc[mt][nt][sub * 2 + 1];
                    *(float2*)(g_gm + (size_t)row * DD + col) = o;
                }
            }
        }
    }
}

extern "C" void kernel_launch(void* const* d_in, const int* in_sizes, int n_in,
                              void* d_out, int out_size) {
    const float* x  = (const float*)d_in[0];
    const int*   ei = (const int*)d_in[1];
    const float* W1 = (const float*)d_in[2];
    const float* b1 = (const float*)d_in[3];
    const float* W2 = (const float*)d_in[4];
    const float* b2 = (const float*)d_in[5];
    const float* Wg = (const float*)d_in[6];
    const float* bg = (const float*)d_in[7];
    float* out = (float*)d_out;

    const int N  = in_sizes[0] / DD;     // 50000
    const int E  = in_sizes[1] / 2;      // 800000
    const int n4 = N * (DD / 4);

    cudaFuncSetAttribute(k_mgemm<0>, cudaFuncAttributeMaxDynamicSharedMemorySize, SMEM_SZ);
    cudaFuncSetAttribute(k_mgemm<1>, cudaFuncAttributeMaxDynamicSharedMemorySize, SMEM_SZ);
    cudaFuncSetAttribute(k_mgemm<2>, cudaFuncAttributeMaxDynamicSharedMemorySize, SMEM_SZ);

    const int TB = 256;
    const int gN4 = (n4 + TB - 1) / TB;
    const int gN  = (N + TB - 1) / TB;
    const int gE  = (E + TB - 1) / TB;
    const int gT  = (N + 127) / 128;
    const int gP  = (N + 7) / 8;

    __nv_bfloat16 *w1h, *w1l, *w2h, *w2l, *wgh, *wgl;
    cudaGetSymbolAddress((void**)&w1h, g_w1h);
    cudaGetSymbolAddress((void**)&w1l, g_w1l);
    cudaGetSymbolAddress((void**)&w2h, g_w2h);
    cudaGetSymbolAddress((void**)&w2l, g_w2l);
    cudaGetSymbolAddress((void**)&wgh, g_wgh);
    cudaGetSymbolAddress((void**)&wgl, g_wgl);

    // prep + CSR build (graph reused by both layers)
    k_prep<<<gN4, TB>>>(x, n4);
    k_cnt_init<<<gN, TB>>>(N);
    k_cnt<<<gE, TB>>>(ei, E);
    k_dinv<<<gN, TB>>>(N);
    k_scan<<<1, 1024>>>(N);
    k_fill<<<gE, TB>>>(ei, E);
    k_wconv<<<(128 * 128 + TB - 1) / TB, TB>>>(W1, w1h, w1l, 128);
    k_wconv<<<(128 * 128 + TB - 1) / TB, TB>>>(W2, w2h, w2l, 128);
    k_wconv<<<(256 * 128 + TB - 1) / TB, TB>>>(Wg, wgh, wgl, 256);

    // layer 1: gm = x0 @ W1; h = relu(pull(gm) + b1)
    k_mgemm<0><<<gT, 256, SMEM_SZ>>>(w1h, w1l, nullptr, nullptr, N);
    k_pull<false><<<gP, 256>>>(b1, N);

    // layer 2: gm = h @ W2; h = relu(pull(gm) + b2) + x0
    k_mgemm<1><<<gT, 256, SMEM_SZ>>>(w2h, w2l, nullptr, nullptr, N);
    k_pull<true><<<gP, 256>>>(b2, N);

    // gate: out = h * sigmoid([h|x0] @ Wg + bg)
    k_mgemm<2><<<gT, 256, SMEM_SZ>>>(wgh, wgl, bg, out, N);
}

// round 9
// speedup vs baseline: 1.2611x; 1.0337x over previous
#include <cuda_runtime.h>
#include <cuda_bf16.h>
#include <math.h>
#include <stdint.h>

#define DD   128
#define NMAX 50000
#define EMAX 800000

// ---- scratch ----
__device__ __align__(16) float g_x0[NMAX * DD];
__device__ __align__(16) float g_gm[NMAX * DD];
__device__ __align__(16) float g_h [NMAX * DD];
__device__ float g_dinv[NMAX];
__device__ int   g_cnt [NMAX];
__device__ int   g_off [NMAX + 1];
__device__ int   g_cur [NMAX];
__device__ __align__(8) int2 g_cs[EMAX];    // {src, norm bits}
// W transposed [n=128][K] bf16 hi/lo splits
__device__ __align__(16) __nv_bfloat16 g_w1h[128 * 128];
__device__ __align__(16) __nv_bfloat16 g_w1l[128 * 128];
__device__ __align__(16) __nv_bfloat16 g_w2h[128 * 128];
__device__ __align__(16) __nv_bfloat16 g_w2l[128 * 128];
__device__ __align__(16) __nv_bfloat16 g_wgh[128 * 256];
__device__ __align__(16) __nv_bfloat16 g_wgl[128 * 256];

__device__ __forceinline__ uint32_t smem_u32(const void* p) {
    uint32_t a;
    asm("{ .reg .u64 t; cvta.to.shared.u64 t, %1; cvt.u32.u64 %0, t; }" : "=r"(a) : "l"(p));
    return a;
}
__device__ __forceinline__ void ldsm4(uint32_t* r, uint32_t addr) {
    asm volatile("ldmatrix.sync.aligned.m8n8.x4.shared.b16 {%0,%1,%2,%3}, [%4];"
        : "=r"(r[0]), "=r"(r[1]), "=r"(r[2]), "=r"(r[3]) : "r"(addr));
}
__device__ __forceinline__ void mma_bf16(float* d, const uint32_t* a, const uint32_t* b) {
    asm volatile("mma.sync.aligned.m16n8k16.row.col.f32.bf16.bf16.f32 "
        "{%0,%1,%2,%3}, {%4,%5,%6,%7}, {%8,%9}, {%0,%1,%2,%3};"
        : "+f"(d[0]), "+f"(d[1]), "+f"(d[2]), "+f"(d[3])
        : "r"(a[0]), "r"(a[1]), "r"(a[2]), "r"(a[3]), "r"(b[0]), "r"(b[1]));
}

// ================= CSR build =================
__global__ void k_cnt(const int* __restrict__ ei, int E) {
    int e = blockIdx.x * blockDim.x + threadIdx.x;
    if (e < E) atomicAdd(&g_cnt[ei[E + e]], 1);
}
__global__ void k_dinv(int N) {
    int i = blockIdx.x * blockDim.x + threadIdx.x;
    if (i < N) g_dinv[i] = rsqrtf(1.0f + (float)g_cnt[i]);   // +1 self-loop
}
__global__ void __launch_bounds__(1024) k_scan(int N) {
    __shared__ int part[1024];
    const int tid = threadIdx.x;
    const int chunk = (N + 1023) / 1024;
    int lo = tid * chunk, hi = min(lo + chunk, N);
    int s = 0;
    for (int i = lo; i < hi; i++) s += g_cnt[i];
    part[tid] = s;
    __syncthreads();
    for (int d = 1; d < 1024; d <<= 1) {
        int t = (tid >= d) ? part[tid - d] : 0;
        __syncthreads();
        part[tid] += t;
        __syncthreads();
    }
    int base = part[tid] - s;
    for (int i = lo; i < hi; i++) {
        g_off[i] = base;
        g_cur[i] = base;
        base += g_cnt[i];
    }
    if (tid == 1023) g_off[N] = base;
}
__global__ void k_fill(const int* __restrict__ ei, int E) {
    int e = blockIdx.x * blockDim.x + threadIdx.x;
    if (e >= E) return;
    int s = ei[e];
    int d = ei[E + e];
    int pos = atomicAdd(&g_cur[d], 1);
    float nm = g_dinv[s] * g_dinv[d];
    g_cs[pos] = make_int2(s, __float_as_int(nm));
}
// all three W: fp32 [K][128] -> transposed [n][K] bf16 hi/lo
__device__ __forceinline__ void wconv1(const float* W, __nv_bfloat16* oh,
                                       __nv_bfloat16* ol, int KW, int i) {
    int k = i / 128, n = i % 128;
    float w = W[i];
    __nv_bfloat16 h = __float2bfloat16(w);
    __nv_bfloat16 l = __float2bfloat16(w - __bfloat162float(h));
    oh[n * KW + k] = h;
    ol[n * KW + k] = l;
}
__global__ void k_wconv_all(const float* __restrict__ W1, const float* __restrict__ W2,
                            const float* __restrict__ Wg) {
    int i = blockIdx.x * blockDim.x + threadIdx.x;
    if (i < 16384)       wconv1(W1, g_w1h, g_w1l, 128, i);
    else if (i < 32768)  wconv1(W2, g_w2h, g_w2l, 128, i - 16384);
    else if (i < 65536)  wconv1(Wg, g_wgh, g_wgl, 256, i - 32768);
}

// ================= pull aggregation (CSR), fused epilogue =================
// g_h[d,:] = relu( gm[d]*dinv[d]^2 + sum_e gm[src_e]*norm_e + bias ) [+ x0[d]]
template <bool ADDX>
__global__ void __launch_bounds__(256) k_pull(const float* __restrict__ bias, int N) {
    const int lane = threadIdx.x & 31;
    const int d = blockIdx.x * 8 + (threadIdx.x >> 5);
    if (d >= N) return;
    float dv = g_dinv[d]; dv *= dv;
    float4 acc = ((const float4*)g_gm)[(size_t)d * 32 + lane];
    acc.x *= dv; acc.y *= dv; acc.z *= dv; acc.w *= dv;
    const int beg = g_off[d], end = g_off[d + 1];
    int i = beg;
    for (; i + 4 <= end; i += 4) {
        int2 m0 = g_cs[i], m1 = g_cs[i + 1], m2 = g_cs[i + 2], m3 = g_cs[i + 3];
        float4 v0 = __ldcg((const float4*)g_gm + (size_t)m0.x * 32 + lane);
        float4 v1 = __ldcg((const float4*)g_gm + (size_t)m1.x * 32 + lane);
        float4 v2 = __ldcg((const float4*)g_gm + (size_t)m2.x * 32 + lane);
        float4 v3 = __ldcg((const float4*)g_gm + (size_t)m3.x * 32 + lane);
        float n0 = __int_as_float(m0.y), n1 = __int_as_float(m1.y);
        float n2 = __int_as_float(m2.y), n3 = __int_as_float(m3.y);
        acc.x += v0.x * n0; acc.y += v0.y * n0; acc.z += v0.z * n0; acc.w += v0.w * n0;
        acc.x += v1.x * n1; acc.y += v1.y * n1; acc.z += v1.z * n1; acc.w += v1.w * n1;
        acc.x += v2.x * n2; acc.y += v2.y * n2; acc.z += v2.z * n2; acc.w += v2.w * n2;
        acc.x += v3.x * n3; acc.y += v3.y * n3; acc.z += v3.z * n3; acc.w += v3.w * n3;
    }
    for (; i < end; i++) {
        int2 m = g_cs[i];
        float4 v = __ldcg((const float4*)g_gm + (size_t)m.x * 32 + lane);
        float nm = __int_as_float(m.y);
        acc.x += v.x * nm; acc.y += v.y * nm; acc.z += v.z * nm; acc.w += v.w * nm;
    }
    float4 b = ((const float4*)bias)[lane];
    float4 o;
    o.x = fmaxf(acc.x + b.x, 0.f);
    o.y = fmaxf(acc.y + b.y, 0.f);
    o.z = fmaxf(acc.z + b.z, 0.f);
    o.w = fmaxf(acc.w + b.w, 0.f);
    if (ADDX) {
        float4 xv = ((const float4*)g_x0)[(size_t)d * 32 + lane];
        o.x += xv.x; o.y += xv.y; o.z += xv.z; o.w += xv.w;
    }
    ((float4*)g_h)[(size_t)d * 32 + lane] = o;
}

// ================= mma.sync split-bf16 GEMM =================
// MODE 0: A=clip(x) -> g_gm, also writes g_x0 = clip(x)
// MODE 1: A=g_h -> g_gm
// MODE 2: A=[g_h | g_x0] -> out = g_h * sigmoid(D + bias)
#define SMEM_SZ 131072

template <int MODE>
__global__ void __launch_bounds__(256, 1)
k_mgemm(const float* __restrict__ Ax,
        const __nv_bfloat16* __restrict__ Wh, const __nv_bfloat16* __restrict__ Wl,
        const float* __restrict__ bias, float* __restrict__ outp, int M) {
    extern __shared__ char smem[];
    char* sAH = smem;
    char* sAL = smem + 32768;
    char* sBH = smem + 65536;
    char* sBL = smem + 98304;
    const uint32_t uAH = smem_u32(sAH);
    const uint32_t uAL = uAH + 32768;
    const uint32_t uBH = uAH + 65536;
    const uint32_t uBL = uAH + 98304;

    const int tid  = threadIdx.x;
    const int lane = tid & 31;
    const int wid  = tid >> 5;
    const int warpM = wid >> 2;
    const int warpN = wid & 3;
    const int rowBase = blockIdx.x * 128;
    constexpr int NH = (MODE == 2) ? 2 : 1;
    constexpr int BK = NH * 128;

    float acc[4][4][4] = {};

    const int rA = warpM * 64 + (lane & 15);
    const int cA = lane >> 4;
    const int nB = warpN * 32 + (lane & 7) + ((lane >> 4) << 3);
    const int cB = (lane >> 3) & 1;

    for (int half = 0; half < NH; half++) {
        {
            const float* A = (MODE == 0) ? Ax : ((MODE == 2 && half == 1) ? g_x0 : g_h);
            int r = tid >> 1;
            int grow = rowBase + r;
            const float* arow = A + (size_t)grow * DD;
            int cb = (tid & 1) * 8;
            bool rok = grow < M;
#pragma unroll
            for (int j = 0; j < 8; j++) {
                int ch = cb + j;
                float4 v0 = make_float4(0.f, 0.f, 0.f, 0.f), v1 = v0;
                if (rok) {
                    v0 = *(const float4*)(arow + ch * 8);
                    v1 = *(const float4*)(arow + ch * 8 + 4);
                }
                if (MODE == 0) {
                    v0.x = fminf(fmaxf(v0.x, -100.f), 100.f);
                    v0.y = fminf(fmaxf(v0.y, -100.f), 100.f);
                    v0.z = fminf(fmaxf(v0.z, -100.f), 100.f);
                    v0.w = fminf(fmaxf(v0.w, -100.f), 100.f);
                    v1.x = fminf(fmaxf(v1.x, -100.f), 100.f);
                    v1.y = fminf(fmaxf(v1.y, -100.f), 100.f);
                    v1.z = fminf(fmaxf(v1.z, -100.f), 100.f);
                    v1.w = fminf(fmaxf(v1.w, -100.f), 100.f);
                    if (rok) {
                        *(float4*)(g_x0 + (size_t)grow * DD + ch * 8) = v0;
                        *(float4*)(g_x0 + (size_t)grow * DD + ch * 8 + 4) = v1;
                    }
                }
                __nv_bfloat162 h0 = __floats2bfloat162_rn(v0.x, v0.y);
                __nv_bfloat162 h1 = __floats2bfloat162_rn(v0.z, v0.w);
                __nv_bfloat162 h2 = __floats2bfloat162_rn(v1.x, v1.y);
                __nv_bfloat162 h3 = __floats2bfloat162_rn(v1.z, v1.w);
                float2 f0 = __bfloat1622float2(h0), f1 = __bfloat1622float2(h1);
                float2 f2 = __bfloat1622float2(h2), f3 = __bfloat1622float2(h3);
                __nv_bfloat162 l0 = __floats2bfloat162_rn(v0.x - f0.x, v0.y - f0.y);
                __nv_bfloat162 l1 = __floats2bfloat162_rn(v0.z - f1.x, v0.w - f1.y);
                __nv_bfloat162 l2 = __floats2bfloat162_rn(v1.x - f2.x, v1.y - f2.y);
                __nv_bfloat162 l3 = __floats2bfloat162_rn(v1.z - f3.x, v1.w - f3.y);
                int addr = r * 256 + ((ch ^ (r & 7)) << 4);
                *(uint4*)(sAH + addr) = make_uint4(*(uint32_t*)&h0, *(uint32_t*)&h1,
                                                   *(uint32_t*)&h2, *(uint32_t*)&h3);
                *(uint4*)(sAL + addr) = make_uint4(*(uint32_t*)&l0, *(uint32_t*)&l1,
                                                   *(uint32_t*)&l2, *(uint32_t*)&l3);
            }
        }
        {
            int n = tid >> 1;
            int cb = (tid & 1) * 8;
            const __nv_bfloat16* bh = Wh + (size_t)n * BK + half * 128;
            const __nv_bfloat16* bl = Wl + (size_t)n * BK + half * 128;
#pragma unroll
            for (int j = 0; j < 8; j++) {
                int ch = cb + j;
                int addr = n * 256 + ((ch ^ (n & 7)) << 4);
                *(uint4*)(sBH + addr) = *(const uint4*)(bh + ch * 8);
                *(uint4*)(sBL + addr) = *(const uint4*)(bl + ch * 8);
            }
        }
        __syncthreads();

#pragma unroll
        for (int ks = 0; ks < 8; ks++) {
            uint32_t afh[4][4], afl[4][4];
            const int swzA = ((ks * 2 + cA) ^ (rA & 7)) << 4;
#pragma unroll
            for (int mt = 0; mt < 4; mt++) {
                int off = (rA + mt * 16) * 256 + swzA;
                ldsm4(afh[mt], uAH + off);
                ldsm4(afl[mt], uAL + off);
            }
            uint32_t bfh[4][2], bfl[4][2];
            const int swzB = ((ks * 2 + cB) ^ (nB & 7)) << 4;
#pragma unroll
            for (int np = 0; np < 2; np++) {
                int off = (nB + np * 16) * 256 + swzB;
                uint32_t t[4];
                ldsm4(t, uBH + off);
                bfh[np * 2][0] = t[0]; bfh[np * 2][1] = t[1];
                bfh[np * 2 + 1][0] = t[2]; bfh[np * 2 + 1][1] = t[3];
                ldsm4(t, uBL + off);
                bfl[np * 2][0] = t[0]; bfl[np * 2][1] = t[1];
                bfl[np * 2 + 1][0] = t[2]; bfl[np * 2 + 1][1] = t[3];
            }
#pragma unroll
            for (int mt = 0; mt < 4; mt++)
#pragma unroll
                for (int nt = 0; nt < 4; nt++) {
                    mma_bf16(acc[mt][nt], afh[mt], bfh[nt]);
                    mma_bf16(acc[mt][nt], afh[mt], bfl[nt]);
                    mma_bf16(acc[mt][nt], afl[mt], bfh[nt]);
                }
        }
        if (NH == 2) __syncthreads();
    }

    const int mbase = rowBase + warpM * 64;
    const int cb0 = warpN * 32 + (lane & 3) * 2;
    const int rl = lane >> 2;
#pragma unroll
    for (int mt = 0; mt < 4; mt++) {
#pragma unroll
        for (int sub = 0; sub < 2; sub++) {
            int row = mbase + mt * 16 + rl + sub * 8;
            if (row >= M) continue;
            if (MODE == 2) {
#pragma unroll
                for (int nt = 0; nt < 4; nt++) {
                    int col = cb0 + nt * 8;
                    float2 b2 = *(const float2*)(bias + col);
                    float2 h2 = *(const float2*)(g_h + (size_t)row * DD + col);
                    float2 o;
                    o.x = h2.x / (1.f + expf(-(acc[mt][nt][sub * 2 + 0] + b2.x)));
                    o.y = h2.y / (1.f + expf(-(acc[mt][nt][sub * 2 + 1] + b2.y)));
                    *(float2*)(outp + (size_t)row * DD + col) = o;
                }
            } else {
#pragma unroll
                for (int nt = 0; nt < 4; nt++) {
                    int col = cb0 + nt * 8;
                    float2 o;
                    o.x = acc[mt][nt][sub * 2 + 0];
                    o.y = acc[mt][nt][sub * 2 + 1];
                    *(float2*)(g_gm + (size_t)row * DD + col) = o;
                }
            }
        }
    }
}

extern "C" void kernel_launch(void* const* d_in, const int* in_sizes, int n_in,
                              void* d_out, int out_size) {
    const float* x  = (const float*)d_in[0];
    const int*   ei = (const int*)d_in[1];
    const float* W1 = (const float*)d_in[2];
    const float* b1 = (const float*)d_in[3];
    const float* W2 = (const float*)d_in[4];
    const float* b2 = (const float*)d_in[5];
    const float* Wg = (const float*)d_in[6];
    const float* bg = (const float*)d_in[7];
    float* out = (float*)d_out;

    const int N = in_sizes[0] / DD;     // 50000
    const int E = in_sizes[1] / 2;      // 800000

    static cudaStream_t s2 = nullptr;
    static cudaEvent_t evFork = nullptr, evJoin = nullptr;
    static int* cntp = nullptr;
    if (!s2) {
        cudaStreamCreateWithFlags(&s2, cudaStreamNonBlocking);
        cudaEventCreateWithFlags(&evFork, cudaEventDisableTiming);
        cudaEventCreateWithFlags(&evJoin, cudaEventDisableTiming);
        cudaGetSymbolAddress((void**)&cntp, g_cnt);
        cudaFuncSetAttribute(k_mgemm<0>, cudaFuncAttributeMaxDynamicSharedMemorySize, SMEM_SZ);
        cudaFuncSetAttribute(k_mgemm<1>, cudaFuncAttributeMaxDynamicSharedMemorySize, SMEM_SZ);
        cudaFuncSetAttribute(k_mgemm<2>, cudaFuncAttributeMaxDynamicSharedMemorySize, SMEM_SZ);
    }

    const int TB = 256;
    const int gN = (N + TB - 1) / TB;
    const int gE = (E + TB - 1) / TB;
    const int gT = (N + 127) / 128;
    const int gP = (N + 7) / 8;

    __nv_bfloat16 *w1h, *w1l, *w2h, *w2l, *wgh, *wgl;
    cudaGetSymbolAddress((void**)&w1h, g_w1h);
    cudaGetSymbolAddress((void**)&w1l, g_w1l);
    cudaGetSymbolAddress((void**)&w2h, g_w2h);
    cudaGetSymbolAddress((void**)&w2l, g_w2l);
    cudaGetSymbolAddress((void**)&wgh, g_wgh);
    cudaGetSymbolAddress((void**)&wgl, g_wgl);

    // ---- fork: CSR build on side stream ----
    cudaEventRecord(evFork, 0);
    cudaStreamWaitEvent(s2, evFork, 0);
    cudaMemsetAsync(cntp, 0, (size_t)N * sizeof(int), s2);
    k_cnt<<<gE, TB, 0, s2>>>(ei, E);
    k_dinv<<<gN, TB, 0, s2>>>(N);
    k_scan<<<1, 1024, 0, s2>>>(N);
    k_fill<<<gE, TB, 0, s2>>>(ei, E);
    cudaEventRecord(evJoin, s2);

    // ---- main stream: weights + layer-1 GEMM (clip fused) ----
    k_wconv_all<<<(65536 + TB - 1) / TB, TB>>>(W1, W2, Wg);
    k_mgemm<0><<<gT, 256, SMEM_SZ>>>(x, w1h, w1l, nullptr, nullptr, N);

    // ---- join: pulls need CSR + dinv ----
    cudaStreamWaitEvent(0, evJoin, 0);
    k_pull<false><<<gP, 256>>>(b1, N);

    // layer 2
    k_mgemm<1><<<gT, 256, SMEM_SZ>>>(nullptr, w2h, w2l, nullptr, nullptr, N);
    k_pull<true><<<gP, 256>>>(b2, N);

    // gate
    k_mgemm<2><<<gT, 256, SMEM_SZ>>>(nullptr, wgh, wgl, bg, out, N);
}